// round 2
// baseline (speedup 1.0000x reference)
#include <cuda_runtime.h>

// CustomLinearRNN: h_t = A4 h_{t-1} + A3 x_t ; known_t = A1 x_t + A2 h_{t-1}
// x:[T,K,B] f32, h0:[H,B], A1:[K,K], A2:[K,H], A3:[H,K], A4:[H,H]
// out: known_seq [T,K,B] then hidden_seq [T,H,B]
//
// One CTA per batch column b. W[192][192] reg-resident (rows 0..127 = h rows
// [A3|A4]; rows 128..191 = known rows [A1|A2]). v[192] = [x_t ; h_{t-1}].
// 8 warps x 32 lanes: lane = row-group (6 rows), warp = j-group (24 j).
// Dot products via packed fma.rn.f32x2 (2 fp32 MAC/instr). Partials reduced
// through smem by 192 threads; v double-buffered; x[t+1] prefetched.

#define T_STEPS 4096
#define KDIM 64
#define HDIM 128
#define BDIM 128
#define NROWS 192
#define NV 192
#define NTHREADS 256
#define NI 6     // rows per thread
#define NJ 24    // j per warp
#define NJ2 12   // f32x2 pairs per warp
#define PARTW 9  // 8 partials + pad (conflict-free reduce: 9 coprime w/ 32)

typedef unsigned long long u64;

__device__ __forceinline__ u64 pk2(float lo, float hi) {
    u64 u; asm("mov.b64 %0, {%1, %2};" : "=l"(u) : "f"(lo), "f"(hi)); return u;
}
__device__ __forceinline__ void upk2(float& lo, float& hi, u64 u) {
    asm("mov.b64 {%0, %1}, %2;" : "=f"(lo), "=f"(hi) : "l"(u));
}
__device__ __forceinline__ u64 ffma2(u64 a, u64 b, u64 c) {
    u64 d; asm("fma.rn.f32x2 %0, %1, %2, %3;" : "=l"(d) : "l"(a), "l"(b), "l"(c));
    return d;
}
__device__ __forceinline__ u64 fadd2(u64 a, u64 b) {
    u64 d; asm("add.rn.f32x2 %0, %1, %2;" : "=l"(d) : "l"(a), "l"(b));
    return d;
}

__device__ __forceinline__ float wval(int R, int J,
                                      const float* __restrict__ A1,
                                      const float* __restrict__ A2,
                                      const float* __restrict__ A3,
                                      const float* __restrict__ A4)
{
    if (R < HDIM) {
        return (J < KDIM) ? A3[R * KDIM + J] : A4[R * HDIM + (J - KDIM)];
    } else {
        const int i = R - HDIM;
        return (J < KDIM) ? A1[i * KDIM + J] : A2[i * HDIM + (J - KDIM)];
    }
}

__global__ __launch_bounds__(NTHREADS, 1)
void rnn_seq_kernel(const float* __restrict__ x,
                    const float* __restrict__ h0,
                    const float* __restrict__ A1,
                    const float* __restrict__ A2,
                    const float* __restrict__ A3,
                    const float* __restrict__ A4,
                    float* __restrict__ out_known,
                    float* __restrict__ out_hidden)
{
    __shared__ __align__(16) float v[2][NV];
    __shared__ float part[NROWS * PARTW];

    const int b    = blockIdx.x;
    const int tid  = threadIdx.x;
    const int lane = tid & 31;   // row group
    const int warp = tid >> 5;   // j group (all lanes share -> smem broadcast)
    const int row0 = lane * NI;
    const int j0   = warp * NJ;

    // ---- register-resident packed weights ----
    u64 w2[NI][NJ2];
    #pragma unroll
    for (int r = 0; r < NI; r++) {
        const int R = row0 + r;
        #pragma unroll
        for (int p = 0; p < NJ2; p++) {
            const int J = j0 + 2 * p;
            w2[r][p] = pk2(wval(R, J, A1, A2, A3, A4),
                           wval(R, J + 1, A1, A2, A3, A4));
        }
    }

    // ---- init v[0] = [x_0 ; h_init] ----
    if (tid < KDIM)            v[0][tid] = x[tid * BDIM + b];
    else if (tid < KDIM + HDIM) v[0][tid] = h0[(tid - KDIM) * BDIM + b];
    __syncthreads();

    #pragma unroll 1
    for (int t = 0; t < T_STEPS; t++) {
        const int cur = t & 1;
        const int nxt = cur ^ 1;

        // prefetch x_{t+1} (threads 192..255); latency hides under FMA block
        float xr = 0.0f;
        if (tid >= NROWS) {
            const int k = tid - NROWS;
            if (t + 1 < T_STEPS)
                xr = x[((size_t)(t + 1) * KDIM + k) * BDIM + b];
        }

        // warp-broadcast read of this warp's 24-value v slice (12 x LDS.64)
        u64 vv[NJ2];
        {
            const u64* vp = reinterpret_cast<const u64*>(&v[cur][j0]);
            #pragma unroll
            for (int p = 0; p < NJ2; p++) vv[p] = vp[p];
        }

        // 6 rows x 12 packed FMAs, two accumulator chains per row
        #pragma unroll
        for (int r = 0; r < NI; r++) {
            u64 a0 = ffma2(w2[r][0], vv[0], pk2(0.0f, 0.0f));
            u64 a1 = ffma2(w2[r][1], vv[1], pk2(0.0f, 0.0f));
            #pragma unroll
            for (int p = 2; p < NJ2; p += 2) {
                a0 = ffma2(w2[r][p],     vv[p],     a0);
                a1 = ffma2(w2[r][p + 1], vv[p + 1], a1);
            }
            a0 = fadd2(a0, a1);
            float slo, shi; upk2(slo, shi, a0);
            part[(row0 + r) * PARTW + warp] = slo + shi;
        }
        __syncthreads();

        // reduce 8 partials per row; write v_next (h) and outputs.
        if (tid < NROWS) {
            const float* p = &part[tid * PARTW];
            const float s = ((p[0] + p[1]) + (p[2] + p[3]))
                          + ((p[4] + p[5]) + (p[6] + p[7]));
            if (tid < HDIM) {
                v[nxt][KDIM + tid] = s;
                out_hidden[(size_t)t * (HDIM * BDIM) + tid * BDIM + b] = s;
            } else {
                out_known[(size_t)t * (KDIM * BDIM) + (tid - HDIM) * BDIM + b] = s;
            }
        } else {
            v[nxt][tid - NROWS] = xr;  // install prefetched x_{t+1}
        }
        __syncthreads();
    }
}

extern "C" void kernel_launch(void* const* d_in, const int* in_sizes, int n_in,
                              void* d_out, int out_size)
{
    const float* x  = (const float*)d_in[0];  // [T,K,B]
    const float* h0 = (const float*)d_in[1];  // [H,B]
    const float* A1 = (const float*)d_in[2];  // [K,K]
    const float* A2 = (const float*)d_in[3];  // [K,H]
    const float* A3 = (const float*)d_in[4];  // [H,K]
    const float* A4 = (const float*)d_in[5];  // [H,H]

    float* out_known  = (float*)d_out;                                   // [T,K,B]
    float* out_hidden = (float*)d_out + (size_t)T_STEPS * KDIM * BDIM;   // [T,H,B]

    rnn_seq_kernel<<<BDIM, NTHREADS>>>(x, h0, A1, A2, A3, A4,
                                       out_known, out_hidden);
    (void)in_sizes; (void)n_in; (void)out_size;
}